// round 15
// baseline (speedup 1.0000x reference)
#include <cuda_runtime.h>
#include <cuda_bf16.h>
#include <mma.h>
#include <math.h>

using namespace nvcuda;

#define NB 32
#define RR 36
#define LL 40
#define DD 1024
#define NPAIR 1024
#define MAXT 40

__device__ float g_q    [NPAIR * MAXT * DD];
__device__ float g_wc   [NPAIR * MAXT * DD];
__device__ float g_lin  [NPAIR * MAXT * DD];
__device__ float g_gate [NPAIR * MAXT * DD];
__device__ float g_qlin [NB * MAXT * DD];
__device__ float g_qgate[NB * MAXT * DD];
__device__ int   g_dup  [NPAIR];
__device__ __nv_bfloat16 g_Ah [NPAIR * MAXT * 2048];
__device__ __nv_bfloat16 g_Al [NPAIR * MAXT * 2048];
__device__ __nv_bfloat16 g_Wlh[1024 * 2048];
__device__ __nv_bfloat16 g_Wll[1024 * 2048];
__device__ __nv_bfloat16 g_Wgh[1024 * 2048];
__device__ __nv_bfloat16 g_Wgl[1024 * 2048];
__device__ __nv_bfloat16 g_Bsh[NB * MAXT * 1024];
__device__ __nv_bfloat16 g_Bsl[NB * MAXT * 1024];

__device__ __forceinline__ float sigf(float x) { return 1.0f / (1.0f + expf(-x)); }

__global__ void k_zero(float* out) {
    int i = blockIdx.x * blockDim.x + threadIdx.x;
    if (i < NPAIR) out[i] = 0.0f;
}

__global__ __launch_bounds__(256) void k_dup(const float* __restrict__ cap, int* __restrict__ dup) {
    int bid = blockIdx.x, c = bid >> 5, k = bid & 31;
    const float4* a = (const float4*)(cap + (size_t)c * LL * DD);
    const float4* b = (const float4*)(cap + (size_t)k * LL * DD);
    float s = 0.f;
    for (int e = threadIdx.x; e < LL * DD / 4; e += 256) {
        float4 x = a[e], y = b[e];
        float dx = x.x - y.x, dy = x.y - y.y, dz = x.z - y.z, dw = x.w - y.w;
        s += dx * dx + dy * dy + dz * dz + dw * dw;
    }
    __shared__ float sm[256];
    sm[threadIdx.x] = s;
    __syncthreads();
    for (int off = 128; off; off >>= 1) {
        if (threadIdx.x < off) sm[threadIdx.x] += sm[threadIdx.x + off];
        __syncthreads();
    }
    if (threadIdx.x == 0) dup[bid] = (c != k && sm[0] <= 1e-6f) ? 1 : 0;
}

__global__ void k_broadcast(const float4* __restrict__ src, float4* __restrict__ q, int T, int selC) {
    long long total = (long long)NPAIR * T * 256;
    for (long long e = (long long)blockIdx.x * blockDim.x + threadIdx.x; e < total;
         e += (long long)gridDim.x * blockDim.x) {
        int d4 = (int)(e & 255);
        long long row = e >> 8;
        int sub = (int)(row % T);
        int pair = (int)(row / T);
        int sel = selC ? (pair >> 5) : (pair & 31);
        q[e] = src[(size_t)(sel * T + sub) * 256 + d4];
    }
}

__global__ void k_conv(const float4* __restrict__ src, __nv_bfloat16* __restrict__ hi,
                       __nv_bfloat16* __restrict__ lo, int rows, int cols4, int dstLd, int dstOff) {
    long long n = (long long)rows * cols4;
    for (long long e = (long long)blockIdx.x * blockDim.x + threadIdx.x; e < n;
         e += (long long)gridDim.x * blockDim.x) {
        int row = (int)(e / cols4);
        int c4 = (int)(e % cols4);
        float4 v = src[e];
        __nv_bfloat16 h0 = __float2bfloat16_rn(v.x);
        __nv_bfloat16 h1 = __float2bfloat16_rn(v.y);
        __nv_bfloat16 h2 = __float2bfloat16_rn(v.z);
        __nv_bfloat16 h3 = __float2bfloat16_rn(v.w);
        __nv_bfloat16 l0 = __float2bfloat16_rn(v.x - __bfloat162float(h0));
        __nv_bfloat16 l1 = __float2bfloat16_rn(v.y - __bfloat162float(h1));
        __nv_bfloat16 l2 = __float2bfloat16_rn(v.z - __bfloat162float(h2));
        __nv_bfloat16 l3 = __float2bfloat16_rn(v.w - __bfloat162float(h3));
        size_t off = (size_t)row * dstLd + dstOff + (size_t)c4 * 4;
        hi[off] = h0;
        hi[off + 1] = h1;
        hi[off + 2] = h2;
        hi[off + 3] = h3;
        lo[off] = l0;
        lo[off + 1] = l1;
        lo[off + 2] = l2;
        lo[off + 3] = l3;
    }
}

// C[m,n] = sum_k (Ah+Al)[m*lda + k] * (Wh+Wl)[n*2048 + woff + k], dropping lo*lo.
// 128x128 block tile, 8 warps (4M x 2N), wmma 16x16x16 bf16, register-prefetch double buffer.
__global__ __launch_bounds__(256) void k_gemm_bf16(
    const __nv_bfloat16* __restrict__ Ah, const __nv_bfloat16* __restrict__ Al, int lda,
    const __nv_bfloat16* __restrict__ Wh, const __nv_bfloat16* __restrict__ Wl, int woff,
    float* __restrict__ C, int K) {
    __shared__ __align__(16) __nv_bfloat16 sAh[128 * 40];
    __shared__ __align__(16) __nv_bfloat16 sAl[128 * 40];
    __shared__ __align__(16) __nv_bfloat16 sBh[128 * 40];
    __shared__ __align__(16) __nv_bfloat16 sBl[128 * 40];

    int tid = threadIdx.x;
    int warp = tid >> 5;
    int wm = warp >> 1;
    int wn = warp & 1;
    int bm = blockIdx.y << 7;
    int bn = blockIdx.x << 7;

    // Per-thread loader slots: 8 chunks of 16B. All arrays fixed-size, fully unrolled.
    const __nv_bfloat16* gp[8];
    __nv_bfloat16* sp[8];
#pragma unroll
    for (int j = 0; j < 8; j++) {
        int c = tid + j * 256;
        int arr = c >> 9;
        int cc = c & 511;
        int row = cc >> 2;
        int q = cc & 3;
        if (arr == 0) {
            gp[j] = Ah + (size_t)(bm + row) * lda + q * 8;
            sp[j] = sAh + row * 40 + q * 8;
        } else if (arr == 1) {
            gp[j] = Al + (size_t)(bm + row) * lda + q * 8;
            sp[j] = sAl + row * 40 + q * 8;
        } else if (arr == 2) {
            gp[j] = Wh + (size_t)(bn + row) * 2048 + woff + q * 8;
            sp[j] = sBh + row * 40 + q * 8;
        } else {
            gp[j] = Wl + (size_t)(bn + row) * 2048 + woff + q * 8;
            sp[j] = sBl + row * 40 + q * 8;
        }
    }

    wmma::fragment<wmma::accumulator, 16, 16, 16, float> acc[2][4];
#pragma unroll
    for (int mi = 0; mi < 2; mi++) {
#pragma unroll
        for (int ni = 0; ni < 4; ni++) {
            wmma::fill_fragment(acc[mi][ni], 0.0f);
        }
    }

    uint4 pf[8];
#pragma unroll
    for (int j = 0; j < 8; j++) {
        pf[j] = *(const uint4*)(gp[j]);
        gp[j] += 32;
    }

    for (int kt = 0; kt < K; kt += 32) {
#pragma unroll
        for (int j = 0; j < 8; j++) {
            *(uint4*)(sp[j]) = pf[j];
        }
        __syncthreads();
        if (kt + 32 < K) {
#pragma unroll
            for (int j = 0; j < 8; j++) {
                pf[j] = *(const uint4*)(gp[j]);
                gp[j] += 32;
            }
        }
#pragma unroll
        for (int ks = 0; ks < 32; ks += 16) {
            wmma::fragment<wmma::matrix_a, 16, 16, 16, __nv_bfloat16, wmma::row_major> ah[2];
            wmma::fragment<wmma::matrix_a, 16, 16, 16, __nv_bfloat16, wmma::row_major> al[2];
            wmma::fragment<wmma::matrix_b, 16, 16, 16, __nv_bfloat16, wmma::col_major> bh[4];
            wmma::fragment<wmma::matrix_b, 16, 16, 16, __nv_bfloat16, wmma::col_major> bl[4];
#pragma unroll
            for (int mi = 0; mi < 2; mi++) {
                int r = wm * 32 + mi * 16;
                wmma::load_matrix_sync(ah[mi], sAh + r * 40 + ks, 40);
                wmma::load_matrix_sync(al[mi], sAl + r * 40 + ks, 40);
            }
#pragma unroll
            for (int ni = 0; ni < 4; ni++) {
                int n0 = wn * 64 + ni * 16;
                wmma::load_matrix_sync(bh[ni], sBh + n0 * 40 + ks, 40);
                wmma::load_matrix_sync(bl[ni], sBl + n0 * 40 + ks, 40);
            }
#pragma unroll
            for (int mi = 0; mi < 2; mi++) {
#pragma unroll
                for (int ni = 0; ni < 4; ni++) {
                    wmma::mma_sync(acc[mi][ni], ah[mi], bh[ni], acc[mi][ni]);
                    wmma::mma_sync(acc[mi][ni], ah[mi], bl[ni], acc[mi][ni]);
                    wmma::mma_sync(acc[mi][ni], al[mi], bh[ni], acc[mi][ni]);
                }
            }
        }
        __syncthreads();
    }
#pragma unroll
    for (int mi = 0; mi < 2; mi++) {
#pragma unroll
        for (int ni = 0; ni < 4; ni++) {
            int row = bm + wm * 32 + mi * 16;
            int col = bn + wn * 64 + ni * 16;
            wmma::store_matrix_sync(C + (size_t)row * 1024 + col, acc[mi][ni], 1024, wmma::mem_row_major);
        }
    }
}

// attn = softmax_s(9 * l2norm_t(leaky(src @ q^T))); wc = attn^T @ src. One block per (c,i).
__global__ __launch_bounds__(256) void k_attn_wc(const float* __restrict__ qbuf,
                                                 const float* __restrict__ ctx,
                                                 float* __restrict__ wcbuf,
                                                 int S, int T, int TT, int srcSelC) {
    __shared__ float srcS[40][33];
    __shared__ float qS[40][33];
    __shared__ float attn[40][41];
    int tid = threadIdx.x, bid = blockIdx.x;
    int c = bid >> 5, i = bid & 31;
    const float* src = ctx + (size_t)(srcSelC ? c : i) * S * DD;
    const float* q = qbuf + (size_t)bid * T * DD;

    float acc[6];
    for (int j = 0; j < 6; j++) acc[j] = 0.f;

    for (int kc = 0; kc < DD; kc += 32) {
        for (int e = tid; e < S * 32; e += 256)
            srcS[e >> 5][e & 31] = src[(size_t)(e >> 5) * DD + kc + (e & 31)];
        for (int e = tid; e < T * 32; e += 256)
            qS[e >> 5][e & 31] = q[(size_t)(e >> 5) * DD + kc + (e & 31)];
        __syncthreads();
#pragma unroll
        for (int j = 0; j < 6; j++) {
            int p = tid + j * 256;
            if (p < S * T) {
                int s = p / T, t = p - s * T;
                float a = acc[j];
#pragma unroll
                for (int kk = 0; kk < 32; kk++) a = fmaf(srcS[s][kk], qS[t][kk], a);
                acc[j] = a;
            }
        }
        __syncthreads();
    }
    for (int j = 0; j < 6; j++) {
        int p = tid + j * 256;
        if (p < S * T) {
            int s = p / T, t = p - s * T;
            float v = acc[j];
            attn[s][t] = (v > 0.f) ? v : 0.1f * v;
        }
    }
    __syncthreads();
    if (tid < S) {
        float sum = 0.f;
        for (int t = 0; t < T; t++) { float v = attn[tid][t]; sum += v * v; }
        float inv = 1.f / (sqrtf(sum) + 1e-8f);
        for (int t = 0; t < T; t++) attn[tid][t] *= inv;
    }
    __syncthreads();
    if (tid < T) {
        float m = -1e30f;
        for (int s = 0; s < S; s++) m = fmaxf(m, attn[s][tid]);
        float sum = 0.f;
        for (int s = 0; s < S; s++) {
            float e = expf(9.0f * (attn[s][tid] - m));
            attn[s][tid] = e;
            sum += e;
        }
        float inv = 1.f / sum;
        for (int s = 0; s < S; s++) attn[s][tid] *= inv;
    }
    __syncthreads();
    const float4* src4 = (const float4*)src;
    float4* wc4 = (float4*)(wcbuf + (size_t)bid * T * DD);
    int grp = tid >> 6;
    int j = tid & 63;
    int tbase = grp * TT;
    for (int d4c = 0; d4c < 4; d4c++) {
        int d4 = d4c * 64 + j;
        float4 a4[10];
#pragma unroll
        for (int tt = 0; tt < 10; tt++) a4[tt] = make_float4(0.f, 0.f, 0.f, 0.f);
        for (int s = 0; s < S; s++) {
            float4 v = __ldg(&src4[s * 256 + d4]);
            const float* arow = &attn[s][tbase];
#pragma unroll
            for (int tt = 0; tt < 10; tt++) {
                if (tt < TT) {
                    float a = arow[tt];
                    a4[tt].x = fmaf(a, v.x, a4[tt].x);
                    a4[tt].y = fmaf(a, v.y, a4[tt].y);
                    a4[tt].z = fmaf(a, v.z, a4[tt].z);
                    a4[tt].w = fmaf(a, v.w, a4[tt].w);
                }
            }
        }
#pragma unroll
        for (int tt = 0; tt < 10; tt++) {
            if (tt < TT) {
                wc4[(tbase + tt) * 256 + d4] = a4[tt];
            }
        }
    }
}

__global__ __launch_bounds__(256) void k_sim(const float* __restrict__ refbuf,
                                             const float* __restrict__ wcbuf,
                                             const int* __restrict__ dup,
                                             float* __restrict__ out, int T, int refSelC) {
    int bid = blockIdx.x, c = bid >> 5, i = bid & 31;
    const float4* ref4 = (const float4*)(refbuf + (size_t)(refSelC ? c : i) * T * DD);
    const float4* wc4 = (const float4*)(wcbuf + (size_t)bid * T * DD);
    int w = threadIdx.x >> 5, lane = threadIdx.x & 31;
    float accsim = 0.f;
    for (int t = w; t < T; t += 8) {
        float dot = 0.f, na = 0.f, nb = 0.f;
        for (int d4 = lane; d4 < 256; d4 += 32) {
            float4 a = ref4[t * 256 + d4];
            float4 b = wc4[t * 256 + d4];
            dot += a.x * b.x + a.y * b.y + a.z * b.z + a.w * b.w;
            na += a.x * a.x + a.y * a.y + a.z * a.z + a.w * a.w;
            nb += b.x * b.x + b.y * b.y + b.z * b.z + b.w * b.w;
        }
#pragma unroll
        for (int off = 16; off; off >>= 1) {
            dot += __shfl_down_sync(0xffffffffu, dot, off);
            na  += __shfl_down_sync(0xffffffffu, na, off);
            nb  += __shfl_down_sync(0xffffffffu, nb, off);
        }
        if (lane == 0) accsim += dot / fmaxf(sqrtf(na) * sqrtf(nb), 1e-8f);
    }
    __shared__ float sm[8];
    if (lane == 0) sm[w] = accsim;
    __syncthreads();
    if (threadIdx.x == 0) {
        float tot = 0.f;
        for (int j = 0; j < 8; j++) tot += sm[j];
        out[bid] += dup[bid] ? -1.0f : (tot / (float)T);
    }
}

__global__ __launch_bounds__(256) void k_update(float* __restrict__ q,
                                                const float* __restrict__ linp,
                                                const float* __restrict__ gatep,
                                                const float* __restrict__ qlin,
                                                const float* __restrict__ qgate,
                                                const float* __restrict__ bl,
                                                const float* __restrict__ bg,
                                                const float* __restrict__ qsrc,
                                                int T, int selC, int isStep0) {
    int row = blockIdx.x;
    int pair = row / T, sub = row - pair * T;
    int sel = selC ? (pair >> 5) : (pair & 31);
    int prow = sel * T + sub;
    int d4 = threadIdx.x;

    const float4* qrow = isStep0 ? (const float4*)(qsrc + (size_t)prow * DD)
                                 : (const float4*)(q + (size_t)row * DD);
    float4 qv = qrow[d4];
    float4 lp = ((const float4*)(linp + (size_t)row * DD))[d4];
    float4 gp = ((const float4*)(gatep + (size_t)row * DD))[d4];
    if (isStep0) {
        float4 ql = ((const float4*)(qlin + (size_t)prow * DD))[d4];
        float4 qg = ((const float4*)(qgate + (size_t)prow * DD))[d4];
        lp.x += ql.x; lp.y += ql.y; lp.z += ql.z; lp.w += ql.w;
        gp.x += qg.x; gp.y += qg.y; gp.z += qg.z; gp.w += qg.w;
    }
    float4 blv = ((const float4*)bl)[d4];
    float4 bgv = ((const float4*)bg)[d4];
    lp.x += blv.x; lp.y += blv.y; lp.z += blv.z; lp.w += blv.w;
    gp.x += bgv.x; gp.y += bgv.y; gp.z += bgv.z; gp.w += bgv.w;

    float4 v;
    float g0 = sigf(gp.x), g1 = sigf(gp.y), g2 = sigf(gp.z), g3 = sigf(gp.w);
    v.x = qv.x * g0 + tanhf(lp.x) * (1.f - g0);
    v.y = qv.y * g1 + tanhf(lp.y) * (1.f - g1);
    v.z = qv.z * g2 + tanhf(lp.z) * (1.f - g2);
    v.w = qv.w * g3 + tanhf(lp.w) * (1.f - g3);

    float ss = v.x * v.x + v.y * v.y + v.z * v.z + v.w * v.w;
    __shared__ float sm[256];
    sm[threadIdx.x] = ss;
    __syncthreads();
    for (int off = 128; off; off >>= 1) {
        if (threadIdx.x < off) sm[threadIdx.x] += sm[threadIdx.x + off];
        __syncthreads();
    }
    float inv = 1.f / (sqrtf(sm[0]) + 1e-8f);
    ((float4*)(q + (size_t)row * DD))[d4] = make_float4(v.x * inv, v.y * inv, v.z * inv, v.w * inv);
}

static inline int convGrid(long long n) {
    long long b = (n + 255) / 256;
    return (int)(b > 8192 ? 8192 : b);
}

static void run_branch(const float* ctx, const float* bsrc, const float* Wl, const float* bl,
                       const float* Wg, const float* bg, float* out, int S, int T, int selC,
                       float* q, float* wc, float* lin, float* gate,
                       float* qlin, float* qgate, int* dup,
                       __nv_bfloat16* Ah, __nv_bfloat16* Al,
                       __nv_bfloat16* Wlh, __nv_bfloat16* Wll,
                       __nv_bfloat16* Wgh, __nv_bfloat16* Wgl,
                       __nv_bfloat16* Bsh, __nv_bfloat16* Bsl) {
    int M = NPAIR * T;
    int Mq = NB * T;
    int TT = T >> 2;
    int srcSelC = selC ^ 1;
    int gW = convGrid(524288);
    int gBs = convGrid((long long)Mq * 256);
    int gM = convGrid((long long)M * 256);
    dim3 gq(8, Mq / 128);
    dim3 gf(8, M / 128);

    k_conv<<<gW, 256>>>((const float4*)Wl, Wlh, Wll, 1024, 512, 2048, 0);
    k_conv<<<gW, 256>>>((const float4*)Wg, Wgh, Wgl, 1024, 512, 2048, 0);
    k_conv<<<gBs, 256>>>((const float4*)bsrc, Bsh, Bsl, Mq, 256, 1024, 0);
    k_broadcast<<<4096, 256>>>((const float4*)bsrc, (float4*)q, T, selC);
    for (int step = 0; step < 3; step++) {
        k_attn_wc<<<NPAIR, 256>>>(q, ctx, wc, S, T, TT, srcSelC);
        k_sim<<<NPAIR, 256>>>(bsrc, wc, dup, out, T, selC);
        if (step == 2) break;
        if (step == 0) {
            k_conv<<<gM, 256>>>((const float4*)wc, Ah, Al, M, 256, 2048, 1024);
            k_gemm_bf16<<<gq, 256>>>(Bsh, Bsl, 1024, Wlh, Wll, 0, qlin, 1024);
            k_gemm_bf16<<<gq, 256>>>(Bsh, Bsl, 1024, Wgh, Wgl, 0, qgate, 1024);
            k_gemm_bf16<<<gf, 256>>>(Ah + 1024, Al + 1024, 2048, Wlh, Wll, 1024, lin, 1024);
            k_gemm_bf16<<<gf, 256>>>(Ah + 1024, Al + 1024, 2048, Wgh, Wgl, 1024, gate, 1024);
            k_update<<<M, 256>>>(q, lin, gate, qlin, qgate, bl, bg, bsrc, T, selC, 1);
        } else {
            k_conv<<<gM, 256>>>((const float4*)q, Ah, Al, M, 256, 2048, 0);
            k_conv<<<gM, 256>>>((const float4*)wc, Ah, Al, M, 256, 2048, 1024);
            k_gemm_bf16<<<gf, 256>>>(Ah, Al, 2048, Wlh, Wll, 0, lin, 2048);
            k_gemm_bf16<<<gf, 256>>>(Ah, Al, 2048, Wgh, Wgl, 0, gate, 2048);
            k_update<<<M, 256>>>(q, lin, gate, qlin, qgate, bl, bg, bsrc, T, selC, 0);
        }
    }
}

extern "C" void kernel_launch(void* const* d_in, const int* in_sizes, int n_in,
                              void* d_out, int out_size) {
    const float* img = (const float*)d_in[0];
    const float* cap = (const float*)d_in[1];
    const float* Wl_t2i = (const float*)d_in[2];
    const float* bl_t2i = (const float*)d_in[3];
    const float* Wg_t2i = (const float*)d_in[4];
    const float* bg_t2i = (const float*)d_in[5];
    const float* Wl_i2t = (const float*)d_in[6];
    const float* bl_i2t = (const float*)d_in[7];
    const float* Wg_i2t = (const float*)d_in[8];
    const float* bg_i2t = (const float*)d_in[9];
    float* out = (float*)d_out;

    float* q;
    float* wc;
    float* lin;
    float* gate;
    float* qlin;
    float* qgate;
    int* dup;
    cudaGetSymbolAddress((void**)&q, g_q);
    cudaGetSymbolAddress((void**)&wc, g_wc);
    cudaGetSymbolAddress((void**)&lin, g_lin);
    cudaGetSymbolAddress((void**)&gate, g_gate);
    cudaGetSymbolAddress((void**)&qlin, g_qlin);
    cudaGetSymbolAddress((void**)&qgate, g_qgate);
    cudaGetSymbolAddress((void**)&dup, g_dup);
    __nv_bfloat16* Ah;
    __nv_bfloat16* Al;
    __nv_bfloat16* Wlh;
    __nv_bfloat16* Wll;
    __nv_bfloat16* Wgh;
    __nv_bfloat16* Wgl;
    __nv_bfloat16* Bsh;
    __nv_bfloat16* Bsl;
    cudaGetSymbolAddress((void**)&Ah, g_Ah);
    cudaGetSymbolAddress((void**)&Al, g_Al);
    cudaGetSymbolAddress((void**)&Wlh, g_Wlh);
    cudaGetSymbolAddress((void**)&Wll, g_Wll);
    cudaGetSymbolAddress((void**)&Wgh, g_Wgh);
    cudaGetSymbolAddress((void**)&Wgl, g_Wgl);
    cudaGetSymbolAddress((void**)&Bsh, g_Bsh);
    cudaGetSymbolAddress((void**)&Bsl, g_Bsl);

    k_zero<<<4, 256>>>(out);
    k_dup<<<NPAIR, 256>>>(cap, dup);

    run_branch(img, cap, Wl_t2i, bl_t2i, Wg_t2i, bg_t2i, out, RR, LL, 1,
               q, wc, lin, gate, qlin, qgate, dup, Ah, Al, Wlh, Wll, Wgh, Wgl, Bsh, Bsl);
    run_branch(cap, img, Wl_i2t, bl_i2t, Wg_i2t, bg_i2t, out, LL, RR, 0,
               q, wc, lin, gate, qlin, qgate, dup, Ah, Al, Wlh, Wll, Wgh, Wgl, Bsh, Bsl);
}

// round 16
// speedup vs baseline: 1.7240x; 1.7240x over previous
#include <cuda_runtime.h>
#include <cuda_bf16.h>
#include <mma.h>
#include <math.h>

using namespace nvcuda;

#define NB 32
#define RR 36
#define LL 40
#define DD 1024
#define NPAIR 1024
#define MAXT 40

__device__ float g_q    [NPAIR * MAXT * DD];
__device__ float g_wc   [NPAIR * MAXT * DD];
__device__ float g_lin  [NPAIR * MAXT * DD];
__device__ float g_gate [NPAIR * MAXT * DD];
__device__ float g_qlin [NB * MAXT * DD];
__device__ float g_qgate[NB * MAXT * DD];
__device__ int   g_dup  [NPAIR];
__device__ __nv_bfloat16 g_Ah [NPAIR * MAXT * 2048];
__device__ __nv_bfloat16 g_Wlh[1024 * 2048];
__device__ __nv_bfloat16 g_Wgh[1024 * 2048];
__device__ __nv_bfloat16 g_Bsh[NB * MAXT * 1024];

__device__ __forceinline__ float sigf(float x) { return 1.0f / (1.0f + expf(-x)); }

__global__ void k_zero(float* out) {
    int i = blockIdx.x * blockDim.x + threadIdx.x;
    if (i < NPAIR) out[i] = 0.0f;
}

__global__ __launch_bounds__(256) void k_dup(const float* __restrict__ cap, int* __restrict__ dup) {
    int bid = blockIdx.x, c = bid >> 5, k = bid & 31;
    const float4* a = (const float4*)(cap + (size_t)c * LL * DD);
    const float4* b = (const float4*)(cap + (size_t)k * LL * DD);
    float s = 0.f;
    for (int e = threadIdx.x; e < LL * DD / 4; e += 256) {
        float4 x = a[e], y = b[e];
        float dx = x.x - y.x, dy = x.y - y.y, dz = x.z - y.z, dw = x.w - y.w;
        s += dx * dx + dy * dy + dz * dz + dw * dw;
    }
    __shared__ float sm[256];
    sm[threadIdx.x] = s;
    __syncthreads();
    for (int off = 128; off; off >>= 1) {
        if (threadIdx.x < off) sm[threadIdx.x] += sm[threadIdx.x + off];
        __syncthreads();
    }
    if (threadIdx.x == 0) dup[bid] = (c != k && sm[0] <= 1e-6f) ? 1 : 0;
}

__global__ void k_broadcast(const float4* __restrict__ src, float4* __restrict__ q, int T, int selC) {
    long long total = (long long)NPAIR * T * 256;
    for (long long e = (long long)blockIdx.x * blockDim.x + threadIdx.x; e < total;
         e += (long long)gridDim.x * blockDim.x) {
        int d4 = (int)(e & 255);
        long long row = e >> 8;
        int sub = (int)(row % T);
        int pair = (int)(row / T);
        int sel = selC ? (pair >> 5) : (pair & 31);
        q[e] = src[(size_t)(sel * T + sub) * 256 + d4];
    }
}

// fp32 -> bf16 conversion (hi only)
__global__ void k_conv(const float4* __restrict__ src, __nv_bfloat16* __restrict__ hi,
                       int rows, int cols4, int dstLd, int dstOff) {
    long long n = (long long)rows * cols4;
    for (long long e = (long long)blockIdx.x * blockDim.x + threadIdx.x; e < n;
         e += (long long)gridDim.x * blockDim.x) {
        int row = (int)(e / cols4);
        int c4 = (int)(e % cols4);
        float4 v = src[e];
        size_t off = (size_t)row * dstLd + dstOff + (size_t)c4 * 4;
        hi[off] = __float2bfloat16_rn(v.x);
        hi[off + 1] = __float2bfloat16_rn(v.y);
        hi[off + 2] = __float2bfloat16_rn(v.z);
        hi[off + 3] = __float2bfloat16_rn(v.w);
    }
}

// C[m,n] = sum_k A[m*lda + k] * W[n*2048 + woff + k], pure bf16, fp32 accum.
// Block tile 128x128, 8 warps (4M x 2N), wmma 16x16x16.
__global__ __launch_bounds__(256) void k_gemm_bf16(
    const __nv_bfloat16* __restrict__ Ah, int lda,
    const __nv_bfloat16* __restrict__ Wh, int woff,
    float* __restrict__ C, int K) {
    __shared__ __align__(16) __nv_bfloat16 sA[128 * 40];
    __shared__ __align__(16) __nv_bfloat16 sB[128 * 40];

    int tid = threadIdx.x;
    int warp = tid >> 5;
    int wm = warp >> 1;
    int wn = warp & 1;
    int bm = blockIdx.y << 7;
    int bn = blockIdx.x << 7;

    wmma::fragment<wmma::accumulator, 16, 16, 16, float> acc[2][4];
    for (int mi = 0; mi < 2; mi++) {
        for (int ni = 0; ni < 4; ni++) {
            wmma::fill_fragment(acc[mi][ni], 0.0f);
        }
    }

    for (int kt = 0; kt < K; kt += 32) {
        __syncthreads();
        for (int j = 0; j < 4; j++) {
            int c = tid + j * 256;
            int arr = c >> 9;
            int cc = c & 511;
            int row = cc >> 2;
            int q = cc & 3;
            const __nv_bfloat16* gsrc;
            __nv_bfloat16* sdst;
            if (arr == 0) {
                gsrc = Ah + (size_t)(bm + row) * lda + kt + q * 8;
                sdst = sA + row * 40 + q * 8;
            } else {
                gsrc = Wh + (size_t)(bn + row) * 2048 + woff + kt + q * 8;
                sdst = sB + row * 40 + q * 8;
            }
            *(uint4*)sdst = *(const uint4*)gsrc;
        }
        __syncthreads();
        for (int ks = 0; ks < 32; ks += 16) {
            wmma::fragment<wmma::matrix_a, 16, 16, 16, __nv_bfloat16, wmma::row_major> ah[2];
            wmma::fragment<wmma::matrix_b, 16, 16, 16, __nv_bfloat16, wmma::col_major> bh[4];
            for (int mi = 0; mi < 2; mi++) {
                int r = wm * 32 + mi * 16;
                wmma::load_matrix_sync(ah[mi], sA + r * 40 + ks, 40);
            }
            for (int ni = 0; ni < 4; ni++) {
                int n0 = wn * 64 + ni * 16;
                wmma::load_matrix_sync(bh[ni], sB + n0 * 40 + ks, 40);
            }
            for (int mi = 0; mi < 2; mi++) {
                for (int ni = 0; ni < 4; ni++) {
                    wmma::mma_sync(acc[mi][ni], ah[mi], bh[ni], acc[mi][ni]);
                }
            }
        }
    }
    for (int mi = 0; mi < 2; mi++) {
        for (int ni = 0; ni < 4; ni++) {
            int row = bm + wm * 32 + mi * 16;
            int col = bn + wn * 64 + ni * 16;
            wmma::store_matrix_sync(C + (size_t)row * 1024 + col, acc[mi][ni], 1024, wmma::mem_row_major);
        }
    }
}

// attn = softmax_s(9 * l2norm_t(leaky(src @ q^T))); wc = attn^T @ src. One block per (c,i).
__global__ __launch_bounds__(256) void k_attn_wc(const float* __restrict__ qbuf,
                                                 const float* __restrict__ ctx,
                                                 float* __restrict__ wcbuf,
                                                 int S, int T, int TT, int srcSelC) {
    __shared__ float srcS[40][33];
    __shared__ float qS[40][33];
    __shared__ float attn[40][41];
    int tid = threadIdx.x, bid = blockIdx.x;
    int c = bid >> 5, i = bid & 31;
    const float* src = ctx + (size_t)(srcSelC ? c : i) * S * DD;
    const float* q = qbuf + (size_t)bid * T * DD;

    float acc[6];
    for (int j = 0; j < 6; j++) acc[j] = 0.f;

    for (int kc = 0; kc < DD; kc += 32) {
        for (int e = tid; e < S * 32; e += 256)
            srcS[e >> 5][e & 31] = src[(size_t)(e >> 5) * DD + kc + (e & 31)];
        for (int e = tid; e < T * 32; e += 256)
            qS[e >> 5][e & 31] = q[(size_t)(e >> 5) * DD + kc + (e & 31)];
        __syncthreads();
#pragma unroll
        for (int j = 0; j < 6; j++) {
            int p = tid + j * 256;
            if (p < S * T) {
                int s = p / T, t = p - s * T;
                float a = acc[j];
#pragma unroll
                for (int kk = 0; kk < 32; kk++) a = fmaf(srcS[s][kk], qS[t][kk], a);
                acc[j] = a;
            }
        }
        __syncthreads();
    }
    for (int j = 0; j < 6; j++) {
        int p = tid + j * 256;
        if (p < S * T) {
            int s = p / T, t = p - s * T;
            float v = acc[j];
            attn[s][t] = (v > 0.f) ? v : 0.1f * v;
        }
    }
    __syncthreads();
    if (tid < S) {
        float sum = 0.f;
        for (int t = 0; t < T; t++) { float v = attn[tid][t]; sum += v * v; }
        float inv = 1.f / (sqrtf(sum) + 1e-8f);
        for (int t = 0; t < T; t++) attn[tid][t] *= inv;
    }
    __syncthreads();
    if (tid < T) {
        float m = -1e30f;
        for (int s = 0; s < S; s++) m = fmaxf(m, attn[s][tid]);
        float sum = 0.f;
        for (int s = 0; s < S; s++) {
            float e = expf(9.0f * (attn[s][tid] - m));
            attn[s][tid] = e;
            sum += e;
        }
        float inv = 1.f / sum;
        for (int s = 0; s < S; s++) attn[s][tid] *= inv;
    }
    __syncthreads();
    const float4* src4 = (const float4*)src;
    float4* wc4 = (float4*)(wcbuf + (size_t)bid * T * DD);
    int grp = tid >> 6;
    int j = tid & 63;
    int tbase = grp * TT;
    for (int d4c = 0; d4c < 4; d4c++) {
        int d4 = d4c * 64 + j;
        float4 a4[10];
#pragma unroll
        for (int tt = 0; tt < 10; tt++) a4[tt] = make_float4(0.f, 0.f, 0.f, 0.f);
        for (int s = 0; s < S; s++) {
            float4 v = __ldg(&src4[s * 256 + d4]);
            const float* arow = &attn[s][tbase];
#pragma unroll
            for (int tt = 0; tt < 10; tt++) {
                if (tt < TT) {
                    float a = arow[tt];
                    a4[tt].x = fmaf(a, v.x, a4[tt].x);
                    a4[tt].y = fmaf(a, v.y, a4[tt].y);
                    a4[tt].z = fmaf(a, v.z, a4[tt].z);
                    a4[tt].w = fmaf(a, v.w, a4[tt].w);
                }
            }
        }
#pragma unroll
        for (int tt = 0; tt < 10; tt++) {
            if (tt < TT) {
                wc4[(tbase + tt) * 256 + d4] = a4[tt];
            }
        }
    }
}

__global__ __launch_bounds__(256) void k_sim(const float* __restrict__ refbuf,
                                             const float* __restrict__ wcbuf,
                                             const int* __restrict__ dup,
                                             float* __restrict__ out, int T, int refSelC) {
    int bid = blockIdx.x, c = bid >> 5, i = bid & 31;
    const float4* ref4 = (const float4*)(refbuf + (size_t)(refSelC ? c : i) * T * DD);
    const float4* wc4 = (const float4*)(wcbuf + (size_t)bid * T * DD);
    int w = threadIdx.x >> 5, lane = threadIdx.x & 31;
    float accsim = 0.f;
    for (int t = w; t < T; t += 8) {
        float dot = 0.f, na = 0.f, nb = 0.f;
        for (int d4 = lane; d4 < 256; d4 += 32) {
            float4 a = ref4[t * 256 + d4];
            float4 b = wc4[t * 256 + d4];
            dot += a.x * b.x + a.y * b.y + a.z * b.z + a.w * b.w;
            na += a.x * a.x + a.y * a.y + a.z * a.z + a.w * a.w;
            nb += b.x * b.x + b.y * b.y + b.z * b.z + b.w * b.w;
        }
#pragma unroll
        for (int off = 16; off; off >>= 1) {
            dot += __shfl_down_sync(0xffffffffu, dot, off);
            na  += __shfl_down_sync(0xffffffffu, na, off);
            nb  += __shfl_down_sync(0xffffffffu, nb, off);
        }
        if (lane == 0) accsim += dot / fmaxf(sqrtf(na) * sqrtf(nb), 1e-8f);
    }
    __shared__ float sm[8];
    if (lane == 0) sm[w] = accsim;
    __syncthreads();
    if (threadIdx.x == 0) {
        float tot = 0.f;
        for (int j = 0; j < 8; j++) tot += sm[j];
        out[bid] += dup[bid] ? -1.0f : (tot / (float)T);
    }
}

__global__ __launch_bounds__(256) void k_update(float* __restrict__ q,
                                                const float* __restrict__ linp,
                                                const float* __restrict__ gatep,
                                                const float* __restrict__ qlin,
                                                const float* __restrict__ qgate,
                                                const float* __restrict__ bl,
                                                const float* __restrict__ bg,
                                                const float* __restrict__ qsrc,
                                                int T, int selC, int isStep0) {
    int row = blockIdx.x;
    int pair = row / T, sub = row - pair * T;
    int sel = selC ? (pair >> 5) : (pair & 31);
    int prow = sel * T + sub;
    int d4 = threadIdx.x;

    const float4* qrow = isStep0 ? (const float4*)(qsrc + (size_t)prow * DD)
                                 : (const float4*)(q + (size_t)row * DD);
    float4 qv = qrow[d4];
    float4 lp = ((const float4*)(linp + (size_t)row * DD))[d4];
    float4 gp = ((const float4*)(gatep + (size_t)row * DD))[d4];
    if (isStep0) {
        float4 ql = ((const float4*)(qlin + (size_t)prow * DD))[d4];
        float4 qg = ((const float4*)(qgate + (size_t)prow * DD))[d4];
        lp.x += ql.x; lp.y += ql.y; lp.z += ql.z; lp.w += ql.w;
        gp.x += qg.x; gp.y += qg.y; gp.z += qg.z; gp.w += qg.w;
    }
    float4 blv = ((const float4*)bl)[d4];
    float4 bgv = ((const float4*)bg)[d4];
    lp.x += blv.x; lp.y += blv.y; lp.z += blv.z; lp.w += blv.w;
    gp.x += bgv.x; gp.y += bgv.y; gp.z += bgv.z; gp.w += bgv.w;

    float4 v;
    float g0 = sigf(gp.x), g1 = sigf(gp.y), g2 = sigf(gp.z), g3 = sigf(gp.w);
    v.x = qv.x * g0 + tanhf(lp.x) * (1.f - g0);
    v.y = qv.y * g1 + tanhf(lp.y) * (1.f - g1);
    v.z = qv.z * g2 + tanhf(lp.z) * (1.f - g2);
    v.w = qv.w * g3 + tanhf(lp.w) * (1.f - g3);

    float ss = v.x * v.x + v.y * v.y + v.z * v.z + v.w * v.w;
    __shared__ float sm[256];
    sm[threadIdx.x] = ss;
    __syncthreads();
    for (int off = 128; off; off >>= 1) {
        if (threadIdx.x < off) sm[threadIdx.x] += sm[threadIdx.x + off];
        __syncthreads();
    }
    float inv = 1.f / (sqrtf(sm[0]) + 1e-8f);
    ((float4*)(q + (size_t)row * DD))[d4] = make_float4(v.x * inv, v.y * inv, v.z * inv, v.w * inv);
}

static inline int convGrid(long long n) {
    long long b = (n + 255) / 256;
    return (int)(b > 8192 ? 8192 : b);
}

static void run_branch(const float* ctx, const float* bsrc, const float* Wl, const float* bl,
                       const float* Wg, const float* bg, float* out, int S, int T, int selC,
                       float* q, float* wc, float* lin, float* gate,
                       float* qlin, float* qgate, int* dup,
                       __nv_bfloat16* Ah, __nv_bfloat16* Wlh, __nv_bfloat16* Wgh,
                       __nv_bfloat16* Bsh) {
    int M = NPAIR * T;
    int Mq = NB * T;
    int TT = T >> 2;
    int srcSelC = selC ^ 1;
    int gW = convGrid(524288);
    int gBs = convGrid((long long)Mq * 256);
    int gM = convGrid((long long)M * 256);
    dim3 gq(8, Mq / 128);
    dim3 gf(8, M / 128);

    k_conv<<<gW, 256>>>((const float4*)Wl, Wlh, 1024, 512, 2048, 0);
    k_conv<<<gW, 256>>>((const float4*)Wg, Wgh, 1024, 512, 2048, 0);
    k_conv<<<gBs, 256>>>((const float4*)bsrc, Bsh, Mq, 256, 1024, 0);
    k_broadcast<<<4096, 256>>>((const float4*)bsrc, (float4*)q, T, selC);
    for (int step = 0; step < 3; step++) {
        k_attn_wc<<<NPAIR, 256>>>(q, ctx, wc, S, T, TT, srcSelC);
        k_sim<<<NPAIR, 256>>>(bsrc, wc, dup, out, T, selC);
        if (step == 2) break;
        if (step == 0) {
            k_conv<<<gM, 256>>>((const float4*)wc, Ah, M, 256, 2048, 1024);
            k_gemm_bf16<<<gq, 256>>>(Bsh, 1024, Wlh, 0, qlin, 1024);
            k_gemm_bf16<<<gq, 256>>>(Bsh, 1024, Wgh, 0, qgate, 1024);
            k_gemm_bf16<<<gf, 256>>>(Ah + 1024, 2048, Wlh, 1024, lin, 1024);
            k_gemm_bf16<<<gf, 256>>>(Ah + 1024, 2048, Wgh, 1024, gate, 1024);
            k_update<<<M, 256>>>(q, lin, gate, qlin, qgate, bl, bg, bsrc, T, selC, 1);
        } else {
            k_conv<<<gM, 256>>>((const float4*)q, Ah, M, 256, 2048, 0);
            k_conv<<<gM, 256>>>((const float4*)wc, Ah, M, 256, 2048, 1024);
            k_gemm_bf16<<<gf, 256>>>(Ah, 2048, Wlh, 0, lin, 2048);
            k_gemm_bf16<<<gf, 256>>>(Ah, 2048, Wgh, 0, gate, 2048);
            k_update<<<M, 256>>>(q, lin, gate, qlin, qgate, bl, bg, bsrc, T, selC, 0);
        }
    }
}

extern "C" void kernel_launch(void* const* d_in, const int* in_sizes, int n_in,
                              void* d_out, int out_size) {
    const float* img = (const float*)d_in[0];
    const float* cap = (const float*)d_in[1];
    const float* Wl_t2i = (const float*)d_in[2];
    const float* bl_t2i = (const float*)d_in[3];
    const float* Wg_t2i = (const float*)d_in[4];
    const float* bg_t2i = (const float*)d_in[5];
    const float* Wl_i2t = (const float*)d_in[6];
    const float* bl_i2t = (const float*)d_in[7];
    const float* Wg_i2t = (const float*)d_in[8];
    const float* bg_i2t = (const float*)d_in[9];
    float* out = (float*)d_out;

    float* q;
    float* wc;
    float* lin;
    float* gate;
    float* qlin;
    float* qgate;
    int* dup;
    cudaGetSymbolAddress((void**)&q, g_q);
    cudaGetSymbolAddress((void**)&wc, g_wc);
    cudaGetSymbolAddress((void**)&lin, g_lin);
    cudaGetSymbolAddress((void**)&gate, g_gate);
    cudaGetSymbolAddress((void**)&qlin, g_qlin);
    cudaGetSymbolAddress((void**)&qgate, g_qgate);
    cudaGetSymbolAddress((void**)&dup, g_dup);
    __nv_bfloat16* Ah;
    __nv_bfloat16* Wlh;
    __nv_bfloat16* Wgh;
    __nv_bfloat16* Bsh;
    cudaGetSymbolAddress((void**)&Ah, g_Ah);
    cudaGetSymbolAddress((void**)&Wlh, g_Wlh);
    cudaGetSymbolAddress((void**)&Wgh, g_Wgh);
    cudaGetSymbolAddress((void**)&Bsh, g_Bsh);

    k_zero<<<4, 256>>>(out);
    k_dup<<<NPAIR, 256>>>(cap, dup);

    run_branch(img, cap, Wl_t2i, bl_t2i, Wg_t2i, bg_t2i, out, RR, LL, 1,
               q, wc, lin, gate, qlin, qgate, dup, Ah, Wlh, Wgh, Bsh);
    run_branch(cap, img, Wl_i2t, bl_i2t, Wg_i2t, bg_i2t, out, LL, RR, 0,
               q, wc, lin, gate, qlin, qgate, dup, Ah, Wlh, Wgh, Bsh);
}